// round 11
// baseline (speedup 1.0000x reference)
#include <cuda_runtime.h>
#include <cfloat>

#define NN 50000
#define DD 128
#define EE 640000
#define RR 200

// ---------------- scratch (device globals; no allocations allowed) ----------
__device__ float g_XS[NN*DD];   // node @ W_s
__device__ float g_XD[NN*DD];   // node @ W_d
__device__ float g_QS[NN*DD];   // node @ (W_s @ w_quad)
__device__ float g_QD[NN*DD];   // node @ (W_d @ w_quad)
__device__ float g_L1[NN*DD];   // node @ loop_weight
__device__ float g_XR[RR*DD];   // rel @ W_r
__device__ float g_QR[RR*DD];   // rel @ (W_r @ w_quad)
__device__ float g_WSQ[DD*DD];
__device__ float g_WDQ[DD*DD];
__device__ float g_WRQ[DD*DD];

__device__ int  g_indeg[NN];
__device__ int  g_off[NN+1];
__device__ int  g_cur[NN];
__device__ int2 g_sorted[EE];   // (src, etype) sorted by dst

// ---------------- packed f32x2 helpers (sm_103a full-rate FMA path) ----------
__device__ __forceinline__ unsigned long long pk2(float lo, float hi) {
    unsigned long long r;
    asm("mov.b64 %0, {%1, %2};" : "=l"(r) : "f"(lo), "f"(hi));
    return r;
}
__device__ __forceinline__ unsigned long long dupf(float a) {
    unsigned long long r;
    asm("mov.b64 %0, {%1, %1};" : "=l"(r) : "f"(a));
    return r;
}
__device__ __forceinline__ void fma2(unsigned long long &d,
                                     unsigned long long a,
                                     unsigned long long b) {
    asm("fma.rn.f32x2 %0, %1, %2, %0;" : "+l"(d) : "l"(a), "l"(b));
}
__device__ __forceinline__ float2 unpk(unsigned long long v) {
    float2 f;
    asm("mov.b64 {%0, %1}, %2;" : "=f"(f.x), "=f"(f.y) : "l"(v));
    return f;
}

// ---------------- init: zero indegree counters -------------------------------
__global__ void init_kernel() {
    int i = blockIdx.x * blockDim.x + threadIdx.x;
    if (i < NN) g_indeg[i] = 0;
}

// ---------------- CSR: count --------------------------------------------------
__global__ void count_kernel(const int* __restrict__ dst) {
    int e = blockIdx.x * blockDim.x + threadIdx.x;
    if (e < EE) atomicAdd(&g_indeg[__ldg(dst + e)], 1);
}

// ---------------- CSR: single-block scan -------------------------------------
__global__ __launch_bounds__(1024) void scan_kernel() {
    __shared__ int sums[1024];
    int t = threadIdx.x;
    const int CH = (NN + 1023) / 1024;     // 49
    int beg = t * CH;
    int end = min(beg + CH, NN);
    int s = 0;
    for (int i = beg; i < end; i++) s += g_indeg[i];
    sums[t] = s;
    __syncthreads();
    for (int off = 1; off < 1024; off <<= 1) {
        int v = (t >= off) ? sums[t - off] : 0;
        __syncthreads();
        sums[t] += v;
        __syncthreads();
    }
    int run = (t == 0) ? 0 : sums[t - 1];
    for (int i = beg; i < end; i++) {
        int c = g_indeg[i];
        g_off[i] = run;
        g_cur[i] = run;
        run += c;
    }
    if (beg <= NN && end == NN) g_off[NN] = run;
}

// ---------------- CSR: scatter -------------------------------------------------
__global__ void scatter_kernel(const int* __restrict__ src,
                               const int* __restrict__ dst,
                               const int* __restrict__ et) {
    int e = blockIdx.x * blockDim.x + threadIdx.x;
    if (e >= EE) return;
    int d = __ldg(dst + e);
    int p = atomicAdd(&g_cur[d], 1);
    g_sorted[p] = make_int2(__ldg(src + e), __ldg(et + e));
}

// ---------------- small GEMM (weights / rel): C[M,128] = A[M,128]@B[128,128] -
__global__ __launch_bounds__(128)
void gemm_kernel(const float* __restrict__ rel,
                 const float* __restrict__ wt, const float* __restrict__ wq,
                 int phase)
{
    const float *A, *B;
    float *C;
    int M;
    int y = blockIdx.y;
    if (phase == 0) {
        M = DD; B = wq;
        if (y == 0)      { A = wt;             C = g_WSQ; }
        else if (y == 1) { A = wt + 2*DD*DD;   C = g_WDQ; }
        else             { A = wt + DD*DD;     C = g_WRQ; }
    } else {
        M = RR;
        if (y == 0) { A = rel; B = wt + DD*DD; C = g_XR; }
        else        { A = rel; B = g_WRQ;      C = g_QR; }
    }
    int row0 = blockIdx.x * 64;
    if (row0 >= M) return;

    __shared__ float As[64][33];
    __shared__ float Bs[32][128];

    int tid = threadIdx.x;
    int tc = tid & 15;
    int tr = tid >> 4;

    unsigned long long acc2[8][4];
    #pragma unroll
    for (int i = 0; i < 8; i++)
        #pragma unroll
        for (int j = 0; j < 4; j++) acc2[i][j] = 0ull;

    for (int kc = 0; kc < DD; kc += 32) {
        #pragma unroll
        for (int i = 0; i < 4; i++) {
            int lin = tid + i*128;
            int r = lin >> 3;
            int kq = (lin & 7) << 2;
            float4 v = make_float4(0.f,0.f,0.f,0.f);
            if (row0 + r < M)
                v = *(const float4*)&A[(row0 + r)*DD + kc + kq];
            As[r][kq]   = v.x;
            As[r][kq+1] = v.y;
            As[r][kq+2] = v.z;
            As[r][kq+3] = v.w;
        }
        #pragma unroll
        for (int i = 0; i < 8; i++) {
            int lin = tid + i*128;
            int r = lin >> 5;
            int cq = (lin & 31) << 2;
            *(float4*)&Bs[r][cq] = *(const float4*)&B[(kc + r)*DD + cq];
        }
        __syncthreads();

        #pragma unroll
        for (int k = 0; k < 32; k++) {
            float a_[8];
            #pragma unroll
            for (int i = 0; i < 8; i++) a_[i] = As[tr*8 + i][k];
            float4 b0 = *(float4*)&Bs[k][tc*8];
            float4 b1 = *(float4*)&Bs[k][tc*8 + 4];
            unsigned long long bb0 = pk2(b0.x, b0.y);
            unsigned long long bb1 = pk2(b0.z, b0.w);
            unsigned long long bb2 = pk2(b1.x, b1.y);
            unsigned long long bb3 = pk2(b1.z, b1.w);
            #pragma unroll
            for (int i = 0; i < 8; i++) {
                unsigned long long pa = dupf(a_[i]);
                fma2(acc2[i][0], pa, bb0);
                fma2(acc2[i][1], pa, bb1);
                fma2(acc2[i][2], pa, bb2);
                fma2(acc2[i][3], pa, bb3);
            }
        }
        __syncthreads();
    }

    #pragma unroll
    for (int i = 0; i < 8; i++) {
        int r = row0 + tr*8 + i;
        if (r < M) {
            float2 f0 = unpk(acc2[i][0]);
            float2 f1 = unpk(acc2[i][1]);
            float2 f2 = unpk(acc2[i][2]);
            float2 f3 = unpk(acc2[i][3]);
            *(float4*)&C[r*DD + tc*8]     = make_float4(f0.x, f0.y, f1.x, f1.y);
            *(float4*)&C[r*DD + tc*8 + 4] = make_float4(f2.x, f2.y, f3.x, f3.y);
        }
    }
}

// ---------------- merged node GEMM: 5 outputs, one A-tile load ---------------
// C_b[64,128] = A[64,128] @ B_b[128,128], b in {W_s, W_d, WSQ, WDQ, lw}.
// A tile staged in smem ONCE; B chunks double-buffered via register prefetch.
// Dynamic smem: As[64][132] + Bs[2][32][128] = 66560 bytes.
#define GEMM5_SMEM (64*132*4 + 2*32*128*4)
__global__ __launch_bounds__(128)
void gemm5_kernel(const float* __restrict__ node,
                  const float* __restrict__ wt,
                  const float* __restrict__ lw)
{
    extern __shared__ float sm[];
    float (*As)[132] = (float(*)[132])sm;
    float (*Bs)[32][128] = (float(*)[32][128])(sm + 64*132);

    int row0 = blockIdx.x * 64;
    int tid = threadIdx.x;
    int tc = tid & 15;
    int tr = tid >> 4;

    const float* Bmat[5] = { wt, wt + 2*DD*DD, g_WSQ, g_WDQ, lw };
    float*       Cmat[5] = { g_XS, g_XD, g_QS, g_QD, g_L1 };

    // stage full 64x128 A tile (once)
    #pragma unroll
    for (int i = 0; i < 16; i++) {
        int lin = tid + i*128;          // one float4 each, 2048 total
        int r = lin >> 5;
        int q = (lin & 31) << 2;
        float4 v = make_float4(0.f,0.f,0.f,0.f);
        if (row0 + r < NN) v = *(const float4*)&node[(row0 + r)*DD + q];
        As[r][q]   = v.x;
        As[r][q+1] = v.y;
        As[r][q+2] = v.z;
        As[r][q+3] = v.w;
    }

    // preload B chunk 0 (matrix 0, kc 0) into buffer 0
    #pragma unroll
    for (int i = 0; i < 8; i++) {
        int lin = tid + i*128;
        int r = lin >> 5;
        int cq = (lin & 31) << 2;
        *(float4*)&Bs[0][r][cq] = *(const float4*)&Bmat[0][r*DD + cq];
    }
    __syncthreads();

    unsigned long long acc2[8][4];
    #pragma unroll
    for (int i = 0; i < 8; i++)
        #pragma unroll
        for (int j = 0; j < 4; j++) acc2[i][j] = 0ull;

    for (int idx = 0; idx < 20; idx++) {        // 5 matrices x 4 k-chunks
        int buf = idx & 1;
        int b   = idx >> 2;
        int kc  = (idx & 3) * 32;

        // register-prefetch next B chunk (L2-hot: only 320KB of B total)
        float4 pf[8];
        if (idx + 1 < 20) {
            int nb  = (idx + 1) >> 2;
            int nkc = ((idx + 1) & 3) * 32;
            const float* B = Bmat[nb];
            #pragma unroll
            for (int i = 0; i < 8; i++) {
                int lin = tid + i*128;
                int r = lin >> 5;
                int cq = (lin & 31) << 2;
                pf[i] = *(const float4*)&B[(nkc + r)*DD + cq];
            }
        }

        // FFMA2 mainloop on current chunk
        #pragma unroll
        for (int k = 0; k < 32; k++) {
            float a_[8];
            #pragma unroll
            for (int i = 0; i < 8; i++) a_[i] = As[tr*8 + i][kc + k];
            float4 b0 = *(float4*)&Bs[buf][k][tc*8];
            float4 b1 = *(float4*)&Bs[buf][k][tc*8 + 4];
            unsigned long long bb0 = pk2(b0.x, b0.y);
            unsigned long long bb1 = pk2(b0.z, b0.w);
            unsigned long long bb2 = pk2(b1.x, b1.y);
            unsigned long long bb3 = pk2(b1.z, b1.w);
            #pragma unroll
            for (int i = 0; i < 8; i++) {
                unsigned long long pa = dupf(a_[i]);
                fma2(acc2[i][0], pa, bb0);
                fma2(acc2[i][1], pa, bb1);
                fma2(acc2[i][2], pa, bb2);
                fma2(acc2[i][3], pa, bb3);
            }
        }

        // commit prefetched chunk into the other buffer
        if (idx + 1 < 20) {
            #pragma unroll
            for (int i = 0; i < 8; i++) {
                int lin = tid + i*128;
                int r = lin >> 5;
                int cq = (lin & 31) << 2;
                *(float4*)&Bs[buf ^ 1][r][cq] = pf[i];
            }
        }
        __syncthreads();

        // end of matrix b: write C, reset acc
        if ((idx & 3) == 3) {
            float* C = Cmat[b];
            #pragma unroll
            for (int i = 0; i < 8; i++) {
                int r = row0 + tr*8 + i;
                if (r < NN) {
                    float2 f0 = unpk(acc2[i][0]);
                    float2 f1 = unpk(acc2[i][1]);
                    float2 f2 = unpk(acc2[i][2]);
                    float2 f3 = unpk(acc2[i][3]);
                    *(float4*)&C[r*DD + tc*8]     = make_float4(f0.x, f0.y, f1.x, f1.y);
                    *(float4*)&C[r*DD + tc*8 + 4] = make_float4(f2.x, f2.y, f3.x, f3.y);
                }
            }
            #pragma unroll
            for (int i = 0; i < 8; i++)
                #pragma unroll
                for (int j = 0; j < 4; j++) acc2[i][j] = 0ull;
        }
    }
}

// ---------------- fused per-node: softmax-agg + loop + LayerNorm -------------
__global__ __launch_bounds__(256)
void node_kernel(const float* __restrict__ norm,
                 const float* __restrict__ node,
                 const float* __restrict__ ew,
                 float* __restrict__ out)
{
    int n = blockIdx.x * 8 + (threadIdx.x >> 5);
    if (n >= NN) return;
    int lane = threadIdx.x & 31;
    int f = lane * 4;
    int base = n * DD + f;

    int start = g_off[n];
    int end   = g_off[n + 1];

    float4 o;
    if (end > start) {
        float4 qd = *(const float4*)&g_QD[base];
        float4 xd = *(const float4*)&g_XD[base];
        float4 den = make_float4(0.f,0.f,0.f,0.f);
        float4 num = make_float4(0.f,0.f,0.f,0.f);

        int2 se = g_sorted[start];
        int sb = se.x * DD + f;
        int rb = se.y * DD + f;
        float4 qs = *(const float4*)&g_QS[sb];
        float4 qr = *(const float4*)&g_QR[rb];
        float4 xs = *(const float4*)&g_XS[sb];
        float4 xr = *(const float4*)&g_XR[rb];

        for (int i = start; i < end; i++) {
            float4 cqs = qs, cqr = qr, cxs = xs, cxr = xr;
            if (i + 1 < end) {
                int2 se2 = g_sorted[i + 1];
                int sb2 = se2.x * DD + f;
                int rb2 = se2.y * DD + f;
                qs = *(const float4*)&g_QS[sb2];
                qr = *(const float4*)&g_QR[rb2];
                xs = *(const float4*)&g_XS[sb2];
                xr = *(const float4*)&g_XR[rb2];
            }
            float a, ex;
            a = cqs.x + cqr.x + qd.x; a = fmaxf(a, 0.01f*a); ex = __expf(a);
            den.x += ex; num.x += ex * (cxs.x + cxr.x + xd.x);
            a = cqs.y + cqr.y + qd.y; a = fmaxf(a, 0.01f*a); ex = __expf(a);
            den.y += ex; num.y += ex * (cxs.y + cxr.y + xd.y);
            a = cqs.z + cqr.z + qd.z; a = fmaxf(a, 0.01f*a); ex = __expf(a);
            den.z += ex; num.z += ex * (cxs.z + cxr.z + xd.z);
            a = cqs.w + cqr.w + qd.w; a = fmaxf(a, 0.01f*a); ex = __expf(a);
            den.w += ex; num.w += ex * (cxs.w + cxr.w + xd.w);
        }
        float nm = __ldg(norm + n);
        float4 l1 = *(const float4*)&g_L1[base];
        o.x = num.x / den.x * nm + l1.x;
        o.y = num.y / den.y * nm + l1.y;
        o.z = num.z / den.z * nm + l1.z;
        o.w = num.w / den.w * nm + l1.w;
    } else {
        // cold path (expected ~0 nodes): evolve loop on the fly
        o = make_float4(0.f,0.f,0.f,0.f);
        const float* nrow = node + n * DD;
        #pragma unroll 4
        for (int k = 0; k < DD; k++) {
            float nv = nrow[k];
            const float* wrow = ew + k * DD + f;
            o.x += nv * wrow[0];
            o.y += nv * wrow[1];
            o.z += nv * wrow[2];
            o.w += nv * wrow[3];
        }
    }

    float s = o.x + o.y + o.z + o.w;
    #pragma unroll
    for (int off = 16; off; off >>= 1) s += __shfl_xor_sync(0xffffffffu, s, off);
    float mu = s * (1.f / DD);

    float cx = o.x - mu, cy = o.y - mu, cz = o.z - mu, cw = o.w - mu;
    float v = cx*cx + cy*cy + cz*cz + cw*cw;
    #pragma unroll
    for (int off = 16; off; off >>= 1) v += __shfl_xor_sync(0xffffffffu, v, off);
    float r = rsqrtf(v * (1.f / DD) + 1e-5f);

    *(float4*)&out[base] = make_float4(cx*r, cy*r, cz*r, cw*r);
}

// ---------------- launch -----------------------------------------------------
extern "C" void kernel_launch(void* const* d_in, const int* in_sizes, int n_in,
                              void* d_out, int out_size)
{
    const float* node = (const float*)d_in[0];
    const float* rel  = (const float*)d_in[1];
    const float* norm = (const float*)d_in[2];
    const float* wt   = (const float*)d_in[3];
    const float* wq   = (const float*)d_in[4];
    const float* lw   = (const float*)d_in[5];
    const float* ew   = (const float*)d_in[6];
    const int*   src  = (const int*)d_in[7];
    const int*   dst  = (const int*)d_in[8];
    const int*   et   = (const int*)d_in[9];
    float* out = (float*)d_out;

    cudaFuncSetAttribute(gemm5_kernel,
                         cudaFuncAttributeMaxDynamicSharedMemorySize, GEMM5_SMEM);

    // combined weights (WSQ/WDQ/WRQ) first — gemm5 and rel-gemm depend on them
    gemm_kernel<<<dim3(2, 3), 128>>>(rel, wt, wq, 0);

    // merged 5-output node GEMM (one A-tile stage, double-buffered B)
    gemm5_kernel<<<(NN + 63)/64, 128, GEMM5_SMEM>>>(node, wt, lw);

    // rel projections (XR, QR), tiny
    gemm_kernel<<<dim3(4, 2), 128>>>(rel, wt, wq, 1);

    // CSR build
    init_kernel<<<(NN + 255)/256, 256>>>();
    count_kernel<<<(EE + 255)/256, 256>>>(dst);
    scan_kernel<<<1, 1024>>>();
    scatter_kernel<<<(EE + 255)/256, 256>>>(src, dst, et);

    // fused edge aggregation + loop + LayerNorm
    node_kernel<<<(NN + 7)/8, 256>>>(norm, node, ew, out);
}

// round 14
// speedup vs baseline: 1.0832x; 1.0832x over previous
#include <cuda_runtime.h>
#include <cfloat>
#include <cstdint>

#define NN 50000
#define DD 128
#define EE 640000
#define RR 200

// ---------------- scratch (device globals; no allocations allowed) ----------
__device__ float g_XS[NN*DD];   // node @ W_s
__device__ float g_XD[NN*DD];   // node @ W_d
__device__ float g_QS[NN*DD];   // node @ (W_s @ w_quad)
__device__ float g_QD[NN*DD];   // node @ (W_d @ w_quad)
__device__ float g_L1[NN*DD];   // node @ loop_weight
__device__ float g_XR[RR*DD];   // rel @ W_r
__device__ float g_QR[RR*DD];   // rel @ (W_r @ w_quad)
__device__ float g_WSQ[DD*DD];
__device__ float g_WDQ[DD*DD];
__device__ float g_WRQ[DD*DD];

__device__ int      g_indeg[NN];
__device__ int      g_off[NN+1];
__device__ int      g_cur[NN];
__device__ unsigned g_sorted[EE];   // src | (etype<<16), sorted by dst

// ---------------- packed f32x2 helpers ---------------------------------------
__device__ __forceinline__ unsigned long long dupf(float a) {
    unsigned long long r;
    asm("mov.b64 %0, {%1, %1};" : "=l"(r) : "f"(a));
    return r;
}
__device__ __forceinline__ void fma2(unsigned long long &d,
                                     unsigned long long a,
                                     unsigned long long b) {
    asm("fma.rn.f32x2 %0, %1, %2, %0;" : "+l"(d) : "l"(a), "l"(b));
}
__device__ __forceinline__ float2 unpk(unsigned long long v) {
    float2 f;
    asm("mov.b64 {%0, %1}, %2;" : "=f"(f.x), "=f"(f.y) : "l"(v));
    return f;
}

// ---------------- shared GEMM tile routine -----------------------------------
// C[row0:row0+64, 0:128] = A[row0:.., 0:128] @ B[128,128]
// 128 threads; thread -> 8 rows x 8 cols; A transposed in smem; f32x2 FMA.
__device__ __forceinline__
void gemm_tile(const float* __restrict__ A, const float* __restrict__ B,
               float* __restrict__ C, int M, int row0)
{
    __shared__ float At[32][68];     // [k][row], padded
    __shared__ float Bs[32][128];

    int tid = threadIdx.x;
    int tc = tid & 15;      // 16 col-groups of 8
    int tr = tid >> 4;      // 8 row-groups of 8

    unsigned long long acc2[8][4];
    #pragma unroll
    for (int i = 0; i < 8; i++)
        #pragma unroll
        for (int j = 0; j < 4; j++) acc2[i][j] = 0ull;

    for (int kc = 0; kc < DD; kc += 32) {
        #pragma unroll
        for (int i = 0; i < 4; i++) {
            int lin = tid + i*128;              // 0..511
            int r = lin >> 3;
            int kq = (lin & 7) << 2;
            float4 v = make_float4(0.f,0.f,0.f,0.f);
            if (row0 + r < M)
                v = *(const float4*)&A[(size_t)(row0 + r)*DD + kc + kq];
            At[kq  ][r] = v.x;
            At[kq+1][r] = v.y;
            At[kq+2][r] = v.z;
            At[kq+3][r] = v.w;
        }
        #pragma unroll
        for (int i = 0; i < 8; i++) {
            int lin = tid + i*128;              // 0..1023
            int r = lin >> 5;
            int cq = (lin & 31) << 2;
            *(float4*)&Bs[r][cq] = *(const float4*)&B[(kc + r)*DD + cq];
        }
        __syncthreads();

        #pragma unroll
        for (int k = 0; k < 32; k++) {
            float4 a0 = *(float4*)&At[k][tr*8];
            float4 a1 = *(float4*)&At[k][tr*8 + 4];
            ulonglong2 b01 = *(ulonglong2*)&Bs[k][tc*8];
            ulonglong2 b23 = *(ulonglong2*)&Bs[k][tc*8 + 4];
            float a_[8] = {a0.x,a0.y,a0.z,a0.w,a1.x,a1.y,a1.z,a1.w};
            #pragma unroll
            for (int i = 0; i < 8; i++) {
                unsigned long long pa = dupf(a_[i]);
                fma2(acc2[i][0], pa, b01.x);
                fma2(acc2[i][1], pa, b01.y);
                fma2(acc2[i][2], pa, b23.x);
                fma2(acc2[i][3], pa, b23.y);
            }
        }
        __syncthreads();
    }

    #pragma unroll
    for (int i = 0; i < 8; i++) {
        int r = row0 + tr*8 + i;
        if (r < M) {
            float2 f0 = unpk(acc2[i][0]);
            float2 f1 = unpk(acc2[i][1]);
            float2 f2 = unpk(acc2[i][2]);
            float2 f3 = unpk(acc2[i][3]);
            *(float4*)&C[(size_t)r*DD + tc*8]     = make_float4(f0.x, f0.y, f1.x, f1.y);
            *(float4*)&C[(size_t)r*DD + tc*8 + 4] = make_float4(f2.x, f2.y, f3.x, f3.y);
        }
    }
}

// ---------------- L1: weight GEMMs + XR GEMM + init(indeg=0) -----------------
// blocks: [0,6) weight gemms, [6,10) XR, [10,...) init
__global__ __launch_bounds__(128)
void phaseA_kernel(const float* __restrict__ rel,
                   const float* __restrict__ wt,
                   const float* __restrict__ wq)
{
    int bid = blockIdx.x;
    if (bid < 6) {
        int y = bid >> 1;           // matrix
        int row0 = (bid & 1) * 64;
        const float* A;
        float* C;
        if (y == 0)      { A = wt;            C = g_WSQ; }
        else if (y == 1) { A = wt + 2*DD*DD;  C = g_WDQ; }
        else             { A = wt + DD*DD;    C = g_WRQ; }
        gemm_tile(A, wq, C, DD, row0);
    } else if (bid < 10) {
        gemm_tile(rel, wt + DD*DD, g_XR, RR, (bid - 6) * 64);
    } else {
        int i = (bid - 10) * 128 + threadIdx.x;
        if (i < NN) g_indeg[i] = 0;
    }
}

// ---------------- L2: 5 node GEMMs + QR GEMM + count -------------------------
#define NTILES ((NN + 63) / 64)     // 782
__global__ __launch_bounds__(128)
void phaseB_kernel(const float* __restrict__ node,
                   const float* __restrict__ rel,
                   const float* __restrict__ wt,
                   const float* __restrict__ lw,
                   const int*   __restrict__ dst)
{
    int bid = blockIdx.x;
    if (bid < 5 * NTILES) {
        int m    = bid % 5;
        int row0 = (bid / 5) * 64;
        const float* B;
        float* C;
        switch (m) {
            case 0: B = wt;           C = g_XS; break;
            case 1: B = wt + 2*DD*DD; C = g_XD; break;
            case 2: B = g_WSQ;        C = g_QS; break;
            case 3: B = g_WDQ;        C = g_QD; break;
            default:B = lw;           C = g_L1; break;
        }
        gemm_tile(node, B, C, NN, row0);
    } else if (bid < 5 * NTILES + 4) {
        gemm_tile(rel, g_WRQ, g_QR, RR, (bid - 5 * NTILES) * 64);
    } else {
        int e = (bid - (5 * NTILES + 4)) * 128 + threadIdx.x;
        if (e < EE) atomicAdd(&g_indeg[__ldg(dst + e)], 1);
    }
}

// ---------------- CSR: single-block scan -------------------------------------
__global__ __launch_bounds__(1024) void scan_kernel() {
    __shared__ int sums[1024];
    int t = threadIdx.x;
    const int CH = (NN + 1023) / 1024;
    int beg = t * CH;
    int end = min(beg + CH, NN);
    int s = 0;
    for (int i = beg; i < end; i++) s += g_indeg[i];
    sums[t] = s;
    __syncthreads();
    for (int off = 1; off < 1024; off <<= 1) {
        int v = (t >= off) ? sums[t - off] : 0;
        __syncthreads();
        sums[t] += v;
        __syncthreads();
    }
    int run = (t == 0) ? 0 : sums[t - 1];
    for (int i = beg; i < end; i++) {
        int c = g_indeg[i];
        g_off[i] = run;
        g_cur[i] = run;
        run += c;
    }
    if (beg <= NN && end == NN) g_off[NN] = run;
}

// ---------------- CSR: scatter (packed src|etype) ----------------------------
__global__ void scatter_kernel(const int* __restrict__ src,
                               const int* __restrict__ dst,
                               const int* __restrict__ et) {
    int e = blockIdx.x * blockDim.x + threadIdx.x;
    if (e >= EE) return;
    int d = __ldg(dst + e);
    int p = atomicAdd(&g_cur[d], 1);
    g_sorted[p] = (unsigned)__ldg(src + e) | ((unsigned)__ldg(et + e) << 16);
}

// ---------------- fused per-node: softmax-agg + loop + LayerNorm -------------
__global__ __launch_bounds__(256)
void node_kernel(const float* __restrict__ norm,
                 const float* __restrict__ node,
                 const float* __restrict__ ew,
                 float* __restrict__ out)
{
    int n = blockIdx.x * 8 + (threadIdx.x >> 5);
    if (n >= NN) return;
    int lane = threadIdx.x & 31;
    int f = lane * 4;
    int base = n * DD + f;

    int start = g_off[n];
    int end   = g_off[n + 1];

    float4 o;
    if (end > start) {
        float4 qd = *(const float4*)&g_QD[base];
        float4 xd = *(const float4*)&g_XD[base];
        float4 den = make_float4(0.f,0.f,0.f,0.f);
        float4 num = make_float4(0.f,0.f,0.f,0.f);

        unsigned se = g_sorted[start];
        int sb = (int)(se & 0xFFFFu) * DD + f;
        int rb = (int)(se >> 16)     * DD + f;
        float4 qs = *(const float4*)&g_QS[sb];
        float4 qr = *(const float4*)&g_QR[rb];
        float4 xs = *(const float4*)&g_XS[sb];
        float4 xr = *(const float4*)&g_XR[rb];

        for (int i = start; i < end; i++) {
            float4 cqs = qs, cqr = qr, cxs = xs, cxr = xr;
            if (i + 1 < end) {
                unsigned se2 = g_sorted[i + 1];
                int sb2 = (int)(se2 & 0xFFFFu) * DD + f;
                int rb2 = (int)(se2 >> 16)     * DD + f;
                qs = *(const float4*)&g_QS[sb2];
                qr = *(const float4*)&g_QR[rb2];
                xs = *(const float4*)&g_XS[sb2];
                xr = *(const float4*)&g_XR[rb2];
            }
            float a, ex;
            a = cqs.x + cqr.x + qd.x; a = fmaxf(a, 0.01f*a); ex = __expf(a);
            den.x += ex; num.x += ex * (cxs.x + cxr.x + xd.x);
            a = cqs.y + cqr.y + qd.y; a = fmaxf(a, 0.01f*a); ex = __expf(a);
            den.y += ex; num.y += ex * (cxs.y + cxr.y + xd.y);
            a = cqs.z + cqr.z + qd.z; a = fmaxf(a, 0.01f*a); ex = __expf(a);
            den.z += ex; num.z += ex * (cxs.z + cxr.z + xd.z);
            a = cqs.w + cqr.w + qd.w; a = fmaxf(a, 0.01f*a); ex = __expf(a);
            den.w += ex; num.w += ex * (cxs.w + cxr.w + xd.w);
        }
        float nm = __ldg(norm + n);
        float4 l1 = *(const float4*)&g_L1[base];
        o.x = num.x / den.x * nm + l1.x;
        o.y = num.y / den.y * nm + l1.y;
        o.z = num.z / den.z * nm + l1.z;
        o.w = num.w / den.w * nm + l1.w;
    } else {
        // cold path (expected ~0 nodes): evolve loop on the fly
        o = make_float4(0.f,0.f,0.f,0.f);
        const float* nrow = node + n * DD;
        #pragma unroll 4
        for (int k = 0; k < DD; k++) {
            float nv = nrow[k];
            const float* wrow = ew + k * DD + f;
            o.x += nv * wrow[0];
            o.y += nv * wrow[1];
            o.z += nv * wrow[2];
            o.w += nv * wrow[3];
        }
    }

    float s = o.x + o.y + o.z + o.w;
    #pragma unroll
    for (int off = 16; off; off >>= 1) s += __shfl_xor_sync(0xffffffffu, s, off);
    float mu = s * (1.f / DD);

    float cx = o.x - mu, cy = o.y - mu, cz = o.z - mu, cw = o.w - mu;
    float v = cx*cx + cy*cy + cz*cz + cw*cw;
    #pragma unroll
    for (int off = 16; off; off >>= 1) v += __shfl_xor_sync(0xffffffffu, v, off);
    float r = rsqrtf(v * (1.f / DD) + 1e-5f);

    *(float4*)&out[base] = make_float4(cx*r, cy*r, cz*r, cw*r);
}

// ---------------- launch -----------------------------------------------------
extern "C" void kernel_launch(void* const* d_in, const int* in_sizes, int n_in,
                              void* d_out, int out_size)
{
    const float* node = (const float*)d_in[0];
    const float* rel  = (const float*)d_in[1];
    const float* norm = (const float*)d_in[2];
    const float* wt   = (const float*)d_in[3];
    const float* wq   = (const float*)d_in[4];
    const float* lw   = (const float*)d_in[5];
    const float* ew   = (const float*)d_in[6];
    const int*   src  = (const int*)d_in[7];
    const int*   dst  = (const int*)d_in[8];
    const int*   et   = (const int*)d_in[9];
    float* out = (float*)d_out;

    // L1: weight gemms (WSQ/WDQ/WRQ) + XR + zero indeg
    phaseA_kernel<<<10 + (NN + 127)/128, 128>>>(rel, wt, wq);

    // L2: 5 node gemms + QR + count  (count hides under the FMA-bound gemms)
    phaseB_kernel<<<5*NTILES + 4 + (EE + 127)/128, 128>>>(node, rel, wt, lw, dst);

    // CSR finish
    scan_kernel<<<1, 1024>>>();
    scatter_kernel<<<(EE + 255)/256, 256>>>(src, dst, et);

    // fused edge aggregation + loop + LayerNorm
    node_kernel<<<(NN + 7)/8, 256>>>(norm, node, ew, out);
}

// round 15
// speedup vs baseline: 1.1792x; 1.0886x over previous
#include <cuda_runtime.h>
#include <cuda_bf16.h>
#include <cfloat>
#include <cstdint>

#define NN 50000
#define DD 128
#define EE 640000
#define RR 200
#define NTILES ((NN + 63) / 64)     // 782

// ---------------- scratch (device globals; no allocations allowed) ----------
__device__ float g_XS[NN*DD];
__device__ float g_XD[NN*DD];
__device__ float g_QS[NN*DD];
__device__ float g_QD[NN*DD];
__device__ float g_L1[NN*DD];
__device__ float g_XR[RR*DD];
__device__ float g_QR[RR*DD];
__device__ float g_WSQ[DD*DD];
__device__ float g_WDQ[DD*DD];
__device__ float g_WRQ[DD*DD];

// bf16 hi/lo split of the 5 node-GEMM B operands, stored as the exact
// swizzled SMEM image: Bt[n][k] (= W[k][n]) with chunk-XOR swizzle.
__device__ __nv_bfloat16 g_Bhi[5*DD*DD];
__device__ __nv_bfloat16 g_Blo[5*DD*DD];

__device__ int      g_indeg[NN];
__device__ int      g_off[NN+1];
__device__ int      g_cur[NN];
__device__ unsigned g_sorted[EE];   // src | (etype<<16), sorted by dst

// swizzled element index inside a [rows x 128] bf16 tile
__host__ __device__ __forceinline__ int swidx(int r, int k) {
    return r * 128 + (((k >> 3) ^ (r & 7)) << 3) + (k & 7);
}

// ---------------- packed f32x2 helpers (small CUDA-core GEMMs) ---------------
__device__ __forceinline__ unsigned long long dupf(float a) {
    unsigned long long r;
    asm("mov.b64 %0, {%1, %1};" : "=l"(r) : "f"(a));
    return r;
}
__device__ __forceinline__ void fma2(unsigned long long &d,
                                     unsigned long long a,
                                     unsigned long long b) {
    asm("fma.rn.f32x2 %0, %1, %2, %0;" : "+l"(d) : "l"(a), "l"(b));
}
__device__ __forceinline__ float2 unpk(unsigned long long v) {
    float2 f;
    asm("mov.b64 {%0, %1}, %2;" : "=f"(f.x), "=f"(f.y) : "l"(v));
    return f;
}

// ---------------- mma helpers ------------------------------------------------
__device__ __forceinline__ void ldsm4(uint32_t &r0, uint32_t &r1,
                                      uint32_t &r2, uint32_t &r3, uint32_t a) {
    asm volatile("ldmatrix.sync.aligned.m8n8.x4.shared.b16 {%0,%1,%2,%3}, [%4];"
        : "=r"(r0), "=r"(r1), "=r"(r2), "=r"(r3) : "r"(a));
}
__device__ __forceinline__ void mma16816(float* c,
        uint32_t a0, uint32_t a1, uint32_t a2, uint32_t a3,
        uint32_t b0, uint32_t b1) {
    asm volatile("mma.sync.aligned.m16n8k16.row.col.f32.bf16.bf16.f32 "
        "{%0,%1,%2,%3}, {%4,%5,%6,%7}, {%8,%9}, {%0,%1,%2,%3};"
        : "+f"(c[0]), "+f"(c[1]), "+f"(c[2]), "+f"(c[3])
        : "r"(a0), "r"(a1), "r"(a2), "r"(a3), "r"(b0), "r"(b1));
}
__device__ __forceinline__ uint32_t smem_u32(const void* p) {
    uint32_t a;
    asm("{ .reg .u64 t; cvta.to.shared.u64 t, %1; cvt.u32.u64 %0, t; }"
        : "=r"(a) : "l"(p));
    return a;
}

// ---------------- shared GEMM tile (fp32 f32x2; weights / rel) --------------
__device__ __forceinline__
void gemm_tile(const float* __restrict__ A, const float* __restrict__ B,
               float* __restrict__ C, int M, int row0)
{
    __shared__ float At[32][68];
    __shared__ float Bs[32][128];

    int tid = threadIdx.x;
    int tc = tid & 15;
    int tr = tid >> 4;

    unsigned long long acc2[8][4];
    #pragma unroll
    for (int i = 0; i < 8; i++)
        #pragma unroll
        for (int j = 0; j < 4; j++) acc2[i][j] = 0ull;

    for (int kc = 0; kc < DD; kc += 32) {
        #pragma unroll
        for (int i = 0; i < 4; i++) {
            int lin = tid + i*128;
            int r = lin >> 3;
            int kq = (lin & 7) << 2;
            float4 v = make_float4(0.f,0.f,0.f,0.f);
            if (row0 + r < M)
                v = *(const float4*)&A[(size_t)(row0 + r)*DD + kc + kq];
            At[kq  ][r] = v.x;
            At[kq+1][r] = v.y;
            At[kq+2][r] = v.z;
            At[kq+3][r] = v.w;
        }
        #pragma unroll
        for (int i = 0; i < 8; i++) {
            int lin = tid + i*128;
            int r = lin >> 5;
            int cq = (lin & 31) << 2;
            *(float4*)&Bs[r][cq] = *(const float4*)&B[(kc + r)*DD + cq];
        }
        __syncthreads();

        #pragma unroll
        for (int k = 0; k < 32; k++) {
            float4 a0 = *(float4*)&At[k][tr*8];
            float4 a1 = *(float4*)&At[k][tr*8 + 4];
            ulonglong2 b01 = *(ulonglong2*)&Bs[k][tc*8];
            ulonglong2 b23 = *(ulonglong2*)&Bs[k][tc*8 + 4];
            float a_[8] = {a0.x,a0.y,a0.z,a0.w,a1.x,a1.y,a1.z,a1.w};
            #pragma unroll
            for (int i = 0; i < 8; i++) {
                unsigned long long pa = dupf(a_[i]);
                fma2(acc2[i][0], pa, b01.x);
                fma2(acc2[i][1], pa, b01.y);
                fma2(acc2[i][2], pa, b23.x);
                fma2(acc2[i][3], pa, b23.y);
            }
        }
        __syncthreads();
    }

    #pragma unroll
    for (int i = 0; i < 8; i++) {
        int r = row0 + tr*8 + i;
        if (r < M) {
            float2 f0 = unpk(acc2[i][0]);
            float2 f1 = unpk(acc2[i][1]);
            float2 f2 = unpk(acc2[i][2]);
            float2 f3 = unpk(acc2[i][3]);
            *(float4*)&C[(size_t)r*DD + tc*8]     = make_float4(f0.x, f0.y, f1.x, f1.y);
            *(float4*)&C[(size_t)r*DD + tc*8 + 4] = make_float4(f2.x, f2.y, f3.x, f3.y);
        }
    }
}

// ---------------- phase A: weight GEMMs + XR + init(indeg=0) -----------------
__global__ __launch_bounds__(128)
void phaseA_kernel(const float* __restrict__ rel,
                   const float* __restrict__ wt,
                   const float* __restrict__ wq)
{
    int bid = blockIdx.x;
    if (bid < 6) {
        int y = bid >> 1;
        int row0 = (bid & 1) * 64;
        const float* A;
        float* C;
        if (y == 0)      { A = wt;            C = g_WSQ; }
        else if (y == 1) { A = wt + 2*DD*DD;  C = g_WDQ; }
        else             { A = wt + DD*DD;    C = g_WRQ; }
        gemm_tile(A, wq, C, DD, row0);
    } else if (bid < 10) {
        gemm_tile(rel, wt + DD*DD, g_XR, RR, (bid - 6) * 64);
    } else {
        int i = (bid - 10) * 128 + threadIdx.x;
        if (i < NN) g_indeg[i] = 0;
    }
}

// ---------------- prep: QR GEMM + B hi/lo split + count ----------------------
// blocks [0,4): QR; [4,644): convert 5 B mats; [644,5644): count
__global__ __launch_bounds__(128)
void prep_kernel(const float* __restrict__ rel,
                 const float* __restrict__ wt,
                 const float* __restrict__ lw,
                 const int*   __restrict__ dst)
{
    int bid = blockIdx.x;
    if (bid < 4) {
        gemm_tile(rel, g_WRQ, g_QR, RR, bid * 64);
    } else if (bid < 644) {
        int m = (bid - 4) >> 7;            // 128 blocks per matrix
        const float* W;
        switch (m) {
            case 0: W = wt;           break;
            case 1: W = wt + 2*DD*DD; break;
            case 2: W = g_WSQ;        break;
            case 3: W = g_WDQ;        break;
            default:W = lw;           break;
        }
        int e = ((bid - 4) & 127) * 128 + threadIdx.x;   // 0..16383
        int n = e >> 7;
        int k = e & 127;
        float v = W[k * DD + n];
        __nv_bfloat16 hi = __float2bfloat16(v);
        __nv_bfloat16 lo = __float2bfloat16(v - __bfloat162float(hi));
        int di = m * DD * DD + swidx(n, k);
        g_Bhi[di] = hi;
        g_Blo[di] = lo;
    } else {
        int e = (bid - 644) * 128 + threadIdx.x;
        if (e < EE) atomicAdd(&g_indeg[__ldg(dst + e)], 1);
    }
}

// ---------------- mma node GEMMs: bf16 hi/lo split, tensor pipe --------------
// CTA 128 threads (4 warps), tile 64 rows x 128 cols, grid 5*NTILES (m = bid%5).
#define SM_AHI 0
#define SM_ALO 16384
#define SM_BHI 32768
#define SM_BLO 65536
#define MMA_SMEM 98304

__global__ __launch_bounds__(128)
void mma_kernel(const float* __restrict__ node)
{
    extern __shared__ char sm[];
    int tid = threadIdx.x;
    int bid = blockIdx.x;
    int m = bid % 5;
    int row0 = (bid / 5) * 64;

    // raw-copy pre-split B (swizzled image), 32KB hi + 32KB lo
    {
        const uint4* srch = (const uint4*)(g_Bhi + m * DD * DD);
        const uint4* srcl = (const uint4*)(g_Blo + m * DD * DD);
        uint4* dsth = (uint4*)(sm + SM_BHI);
        uint4* dstl = (uint4*)(sm + SM_BLO);
        #pragma unroll
        for (int i = 0; i < 16; i++) {
            int idx = tid + i * 128;         // 2048 uint4
            dsth[idx] = srch[idx];
            dstl[idx] = srcl[idx];
        }
    }
    // split A tile (64x128 fp32 -> bf16 hi/lo, swizzled)
    {
        int r = tid >> 1;
        int k0 = (tid & 1) * 64;
        int gr = row0 + r;
        const float* arow = node + (size_t)gr * DD;
        __nv_bfloat162* ah = (__nv_bfloat162*)(sm + SM_AHI);
        __nv_bfloat162* al = (__nv_bfloat162*)(sm + SM_ALO);
        #pragma unroll 8
        for (int k = k0; k < k0 + 64; k += 2) {
            float2 v = (gr < NN) ? *(const float2*)&arow[k] : make_float2(0.f, 0.f);
            __nv_bfloat162 hi, lo;
            hi.x = __float2bfloat16(v.x);
            hi.y = __float2bfloat16(v.y);
            lo.x = __float2bfloat16(v.x - __bfloat162float(hi.x));
            lo.y = __float2bfloat16(v.y - __bfloat162float(hi.y));
            int idx = swidx(r, k) >> 1;      // element pair index
            ah[idx] = hi;
            al[idx] = lo;
        }
    }
    __syncthreads();

    int warp = tid >> 5;
    int lane = tid & 31;
    int q  = lane >> 3;        // which 8x8 matrix this lane addresses
    int rr = lane & 7;

    uint32_t base = smem_u32(sm);
    // A ldmatrix row/addr components: lane -> row warp*16 + (q&1)*8 + rr
    uint32_t arow = (uint32_t)(warp * 16 + ((q & 1) << 3) + rr);
    uint32_t axor = (arow & 7) << 4;
    uint32_t abase = base + arow * 256;
    // B: lane -> row np*16 + (q>>1)*8 + rr, chunk 2*ks + (q&1)
    uint32_t brr = (uint32_t)(((q >> 1) << 3) + rr);
    uint32_t bsel = (uint32_t)(q & 1);

    float c[16][4];
    #pragma unroll
    for (int j = 0; j < 16; j++)
        #pragma unroll
        for (int x = 0; x < 4; x++) c[j][x] = 0.f;

    #pragma unroll
    for (int ks = 0; ks < 8; ks++) {
        uint32_t achunk = (uint32_t)(2 * ks + (q >> 1));
        uint32_t aoff = ((achunk << 4) ^ axor);
        uint32_t ah0, ah1, ah2, ah3, al0, al1, al2, al3;
        ldsm4(ah0, ah1, ah2, ah3, abase + SM_AHI + aoff);
        ldsm4(al0, al1, al2, al3, abase + SM_ALO + aoff);

        #pragma unroll
        for (int np = 0; np < 8; np++) {
            uint32_t brow = (uint32_t)(np * 16) + brr;
            uint32_t bchunk = (uint32_t)(2 * ks) + bsel;
            uint32_t boff = brow * 256 + (((bchunk << 4)) ^ ((brow & 7) << 4));
            uint32_t bh0, bh1, bh2, bh3, bl0, bl1, bl2, bl3;
            ldsm4(bh0, bh1, bh2, bh3, base + SM_BHI + boff);
            ldsm4(bl0, bl1, bl2, bl3, base + SM_BLO + boff);

            mma16816(c[2*np],   ah0, ah1, ah2, ah3, bh0, bh1);
            mma16816(c[2*np+1], ah0, ah1, ah2, ah3, bh2, bh3);
            mma16816(c[2*np],   ah0, ah1, ah2, ah3, bl0, bl1);
            mma16816(c[2*np+1], ah0, ah1, ah2, ah3, bl2, bl3);
            mma16816(c[2*np],   al0, al1, al2, al3, bh0, bh1);
            mma16816(c[2*np+1], al0, al1, al2, al3, bh2, bh3);
        }
    }

    // epilogue
    float* C;
    switch (m) {
        case 0: C = g_XS; break;
        case 1: C = g_XD; break;
        case 2: C = g_QS; break;
        case 3: C = g_QD; break;
        default:C = g_L1; break;
    }
    int g  = lane >> 2;
    int t2 = (lane & 3) * 2;
    int gr0 = row0 + warp * 16 + g;
    int gr1 = gr0 + 8;
    #pragma unroll
    for (int j = 0; j < 16; j++) {
        int col = j * 8 + t2;
        if (gr0 < NN) *(float2*)&C[(size_t)gr0 * DD + col] = make_float2(c[j][0], c[j][1]);
        if (gr1 < NN) *(float2*)&C[(size_t)gr1 * DD + col] = make_float2(c[j][2], c[j][3]);
    }
}

// ---------------- CSR: single-block scan -------------------------------------
__global__ __launch_bounds__(1024) void scan_kernel() {
    __shared__ int sums[1024];
    int t = threadIdx.x;
    const int CH = (NN + 1023) / 1024;
    int beg = t * CH;
    int end = min(beg + CH, NN);
    int s = 0;
    for (int i = beg; i < end; i++) s += g_indeg[i];
    sums[t] = s;
    __syncthreads();
    for (int off = 1; off < 1024; off <<= 1) {
        int v = (t >= off) ? sums[t - off] : 0;
        __syncthreads();
        sums[t] += v;
        __syncthreads();
    }
    int run = (t == 0) ? 0 : sums[t - 1];
    for (int i = beg; i < end; i++) {
        int c = g_indeg[i];
        g_off[i] = run;
        g_cur[i] = run;
        run += c;
    }
    if (beg <= NN && end == NN) g_off[NN] = run;
}

// ---------------- CSR: scatter (packed src|etype) ----------------------------
__global__ void scatter_kernel(const int* __restrict__ src,
                               const int* __restrict__ dst,
                               const int* __restrict__ et) {
    int e = blockIdx.x * blockDim.x + threadIdx.x;
    if (e >= EE) return;
    int d = __ldg(dst + e);
    int p = atomicAdd(&g_cur[d], 1);
    g_sorted[p] = (unsigned)__ldg(src + e) | ((unsigned)__ldg(et + e) << 16);
}

// ---------------- fused per-node: softmax-agg + loop + LayerNorm -------------
__global__ __launch_bounds__(256)
void node_kernel(const float* __restrict__ norm,
                 const float* __restrict__ node,
                 const float* __restrict__ ew,
                 float* __restrict__ out)
{
    int n = blockIdx.x * 8 + (threadIdx.x >> 5);
    if (n >= NN) return;
    int lane = threadIdx.x & 31;
    int f = lane * 4;
    int base = n * DD + f;

    int start = g_off[n];
    int end   = g_off[n + 1];

    float4 o;
    if (end > start) {
        float4 qd = *(const float4*)&g_QD[base];
        float4 xd = *(const float4*)&g_XD[base];
        float4 den = make_float4(0.f,0.f,0.f,0.f);
        float4 num = make_float4(0.f,0.f,0.f,0.f);

        unsigned se = g_sorted[start];
        int sb = (int)(se & 0xFFFFu) * DD + f;
        int rb = (int)(se >> 16)     * DD + f;
        float4 qs = *(const float4*)&g_QS[sb];
        float4 qr = *(const float4*)&g_QR[rb];
        float4 xs = *(const float4*)&g_XS[sb];
        float4 xr = *(const float4*)&g_XR[rb];

        for (int i = start; i < end; i++) {
            float4 cqs = qs, cqr = qr, cxs = xs, cxr = xr;
            if (i + 1 < end) {
                unsigned se2 = g_sorted[i + 1];
                int sb2 = (int)(se2 & 0xFFFFu) * DD + f;
                int rb2 = (int)(se2 >> 16)     * DD + f;
                qs = *(const float4*)&g_QS[sb2];
                qr = *(const float4*)&g_QR[rb2];
                xs = *(const float4*)&g_XS[sb2];
                xr = *(const float4*)&g_XR[rb2];
            }
            float a, ex;
            a = cqs.x + cqr.x + qd.x; a = fmaxf(a, 0.01f*a); ex = __expf(a);
            den.x += ex; num.x += ex * (cxs.x + cxr.x + xd.x);
            a = cqs.y + cqr.y + qd.y; a = fmaxf(a, 0.01f*a); ex = __expf(a);
            den.y += ex; num.y += ex * (cxs.y + cxr.y + xd.y);
            a = cqs.z + cqr.z + qd.z; a = fmaxf(a, 0.01f*a); ex = __expf(a);
            den.z += ex; num.z += ex * (cxs.z + cxr.z + xd.z);
            a = cqs.w + cqr.w + qd.w; a = fmaxf(a, 0.01f*a); ex = __expf(a);
            den.w += ex; num.w += ex * (cxs.w + cxr.w + xd.w);
        }
        float nm = __ldg(norm + n);
        float4 l1 = *(const float4*)&g_L1[base];
        o.x = num.x / den.x * nm + l1.x;
        o.y = num.y / den.y * nm + l1.y;
        o.z = num.z / den.z * nm + l1.z;
        o.w = num.w / den.w * nm + l1.w;
    } else {
        o = make_float4(0.f,0.f,0.f,0.f);
        const float* nrow = node + n * DD;
        #pragma unroll 4
        for (int k = 0; k < DD; k++) {
            float nv = nrow[k];
            const float* wrow = ew + k * DD + f;
            o.x += nv * wrow[0];
            o.y += nv * wrow[1];
            o.z += nv * wrow[2];
            o.w += nv * wrow[3];
        }
    }

    float s = o.x + o.y + o.z + o.w;
    #pragma unroll
    for (int off = 16; off; off >>= 1) s += __shfl_xor_sync(0xffffffffu, s, off);
    float mu = s * (1.f / DD);

    float cx = o.x - mu, cy = o.y - mu, cz = o.z - mu, cw = o.w - mu;
    float v = cx*cx + cy*cy + cz*cz + cw*cw;
    #pragma unroll
    for (int off = 16; off; off >>= 1) v += __shfl_xor_sync(0xffffffffu, v, off);
    float r = rsqrtf(v * (1.f / DD) + 1e-5f);

    *(float4*)&out[base] = make_float4(cx*r, cy*r, cz*r, cw*r);
}

// ---------------- launch -----------------------------------------------------
extern "C" void kernel_launch(void* const* d_in, const int* in_sizes, int n_in,
                              void* d_out, int out_size)
{
    const float* node = (const float*)d_in[0];
    const float* rel  = (const float*)d_in[1];
    const float* norm = (const float*)d_in[2];
    const float* wt   = (const float*)d_in[3];
    const float* wq   = (const float*)d_in[4];
    const float* lw   = (const float*)d_in[5];
    const float* ew   = (const float*)d_in[6];
    const int*   src  = (const int*)d_in[7];
    const int*   dst  = (const int*)d_in[8];
    const int*   et   = (const int*)d_in[9];
    float* out = (float*)d_out;

    cudaFuncSetAttribute(mma_kernel,
                         cudaFuncAttributeMaxDynamicSharedMemorySize, MMA_SMEM);

    // A: weight gemms (WSQ/WDQ/WRQ) + XR + zero indeg
    phaseA_kernel<<<10 + (NN + 127)/128, 128>>>(rel, wt, wq);

    // prep: QR gemm + bf16 hi/lo split of 5 B mats + indegree count
    prep_kernel<<<644 + (EE + 127)/128, 128>>>(rel, wt, lw, dst);

    // tensor-pipe node GEMMs: XS, XD, QS, QD, L1
    mma_kernel<<<5*NTILES, 128, MMA_SMEM>>>(node);

    // CSR finish
    scan_kernel<<<1, 1024>>>();
    scatter_kernel<<<(EE + 255)/256, 256>>>(src, dst, et);

    // fused edge aggregation + loop + LayerNorm
    node_kernel<<<(NN + 7)/8, 256>>>(norm, node, ew, out);
}